// round 14
// baseline (speedup 1.0000x reference)
#include <cuda_runtime.h>
#include <cuda_bf16.h>
#include <cstdint>

// Problem dims
#define Bdim 4
#define Mdim 256
#define Ndim 128
#define Ddim 512
#define Cdim 1024
#define ROWS (Bdim*Mdim*Ndim)   // 131072

// -------- scratch (device globals) --------
__device__ float g_he[Bdim*Mdim*Ddim];          // 2 MB
__device__ float g_hd[Bdim*Ndim*Ddim];          // 1 MB
__device__ __nv_bfloat16 g_w2b[Cdim*Ddim];      // 1 MB   w2 -> bf16

// -------- helpers --------
__device__ __forceinline__ float tanh_fast(float x){
    float r; asm("tanh.approx.f32 %0, %1;" : "=f"(r) : "f"(x)); return r;
}
__device__ __forceinline__ unsigned pk(float lo, float hi){
    unsigned r;
    asm("cvt.rn.bf16x2.f32 %0, %2, %1;" : "=r"(r) : "f"(lo), "f"(hi));
    return r;
}
__device__ __forceinline__ void mma_bf16(float* d, const unsigned* a, const unsigned* b){
    asm volatile(
        "mma.sync.aligned.m16n8k16.row.col.f32.bf16.bf16.f32 "
        "{%0,%1,%2,%3}, {%4,%5,%6,%7}, {%8,%9}, {%0,%1,%2,%3};\n"
        : "+f"(d[0]), "+f"(d[1]), "+f"(d[2]), "+f"(d[3])
        : "r"(a[0]), "r"(a[1]), "r"(a[2]), "r"(a[3]), "r"(b[0]), "r"(b[1]));
}
__device__ __forceinline__ void ldsm4(unsigned* r, unsigned addr){
    asm volatile("ldmatrix.sync.aligned.m8n8.x4.shared.b16 {%0,%1,%2,%3}, [%4];"
        : "=r"(r[0]), "=r"(r[1]), "=r"(r[2]), "=r"(r[3]) : "r"(addr));
}
__device__ __forceinline__ unsigned smem_u32(const void* p){
    unsigned a;
    asm("{ .reg .u64 t; cvta.to.shared.u64 t, %1; cvt.u32.u64 %0, t; }" : "=r"(a) : "l"(p));
    return a;
}
__device__ __forceinline__ void cpa16(unsigned saddr, const void* g){
    asm volatile("cp.async.cg.shared.global [%0], [%1], 16;" :: "r"(saddr), "l"(g));
}
#define CPA_COMMIT() asm volatile("cp.async.commit_group;" ::: "memory")
#define CPA_WAIT0()  asm volatile("cp.async.wait_group 0;" ::: "memory")

// ================= K0: w2 -> bf16 =================
__global__ __launch_bounds__(256) void cvtw2b_k(const float* __restrict__ w2){
    const int i = blockIdx.x*256 + threadIdx.x;
    float4 v0 = ((const float4*)w2)[2*i];
    float4 v1 = ((const float4*)w2)[2*i + 1];
    uint4 o;
    o.x = pk(v0.x, v0.y); o.y = pk(v0.z, v0.w);
    o.z = pk(v1.x, v1.y); o.w = pk(v1.z, v1.w);
    ((uint4*)g_w2b)[i] = o;
}

// ================= K1: fc1 both GEMMs in one launch (fp32, exact) ==============
__global__ __launch_bounds__(256) void fc1_k(const float* __restrict__ enc,
                                             const float* __restrict__ dec,
                                             const float* __restrict__ W){
    __shared__ float sX[16][64];
    __shared__ float sW[16][64];
    const int by = blockIdx.y;
    const int which = (by >= 16);
    const float* __restrict__ X = which ? dec : enc;
    float* __restrict__ Y = which ? g_hd : g_he;
    const int woff = which ? Ddim : 0;
    const int rb = (which ? (by - 16) : by) << 6;
    const int t  = threadIdx.x;
    const int tx = t & 15, ty = t >> 4;
    const int eb = blockIdx.x << 6;
    const int r  = t >> 2, kq = (t & 3) << 2;

    float acc[4][4];
#pragma unroll
    for (int i = 0; i < 4; i++)
#pragma unroll
        for (int j = 0; j < 4; j++) acc[i][j] = 0.f;

    for (int k0 = 0; k0 < Ddim; k0 += 16){
        float4 xv = *(const float4*)(X + (rb + r)*Ddim + k0 + kq);
        float4 wv = *(const float4*)(W + (eb + r)*(2*Ddim) + woff + k0 + kq);
        __syncthreads();
        sX[kq+0][r] = xv.x; sX[kq+1][r] = xv.y; sX[kq+2][r] = xv.z; sX[kq+3][r] = xv.w;
        sW[kq+0][r] = wv.x; sW[kq+1][r] = wv.y; sW[kq+2][r] = wv.z; sW[kq+3][r] = wv.w;
        __syncthreads();
#pragma unroll
        for (int k = 0; k < 16; k++){
            float4 a  = *(const float4*)&sX[k][ty << 2];
            float4 bv = *(const float4*)&sW[k][tx << 2];
            float av[4] = {a.x, a.y, a.z, a.w};
            float bb[4] = {bv.x, bv.y, bv.z, bv.w};
#pragma unroll
            for (int i = 0; i < 4; i++)
#pragma unroll
                for (int j = 0; j < 4; j++) acc[i][j] = fmaf(av[i], bb[j], acc[i][j]);
        }
    }
#pragma unroll
    for (int i = 0; i < 4; i++)
#pragma unroll
        for (int j = 0; j < 4; j++)
            Y[(rb + (ty<<2) + i)*Ddim + eb + (tx<<2) + j] = acc[i][j];
}

// ================= K2: fused tanh + GEMM + log-softmax =========================
// One CTA per bm (grid 1024), 512 threads, 16 warps as 2(m) x 8(n),
// warp tile 64x32. 128 rows x ALL 1024 cols in 4 col-passes of 256.
// K=512 in 8 chunks of 64. A produced in-kernel (pass 0), hd prefetched
// one chunk ahead in registers so tanh+STS never waits on LDG.
// smem: sA 8x18432 = 147456, sB 2x36864 = 73728, sHE 2048  (= 223232)
#define PITCH   144
#define ACHUNK  18432
#define SB_OFF  147456
#define B_BUF   36864
#define SHE_OFF 221184
#define SMEM_TOT 223232

__global__ __launch_bounds__(512,1) void fused_k(const float* __restrict__ b1,
                                                 const float* __restrict__ b2,
                                                 float* __restrict__ out){
    extern __shared__ __align__(128) char smemc[];
    const unsigned sb = smem_u32(smemc);

    const int bm  = blockIdx.x;     // 0..1023
    const int g0  = bm << 7;        // first global row
    const int b   = bm >> 8;        // batch
    const int t   = threadIdx.x;
    const int w   = t >> 5, l = t & 31;
    const int wm  = w >> 3, wn = w & 7;      // 2(m) x 8(n)
    const int lq  = l >> 2, lr = l & 3;

    float* sHE = (float*)(smemc + SHE_OFF);

    // ldmatrix per-lane base offsets
    const unsigned aLane = (unsigned)((l & 15)*PITCH + (l & 16));
    const unsigned bLane = (unsigned)(((l & 7) + ((l & 16) >> 1))*PITCH + ((l & 8) << 1));
    const unsigned aBase = (unsigned)((wm << 6)*PITCH) + aLane;
    const unsigned bBase = (unsigned)((wn << 5)*PITCH) + bLane;

    // B producer mapping: 8 threads per 128B row chunk; rows (t>>3) + 64j, j<4
    const int pr  = t >> 3;          // 0..63
    const int pc  = (t & 7) << 4;
    const char* bG = (const char*)g_w2b + ((size_t)pr << 10) + pc;
    const unsigned sBp = sb + SB_OFF + pr*PITCH + pc;

    // A producer mapping: rows (t>>4) + 32i (i<4), float4 slot t&15
    const int arb = t >> 4;          // 0..31
    const int af4 = t & 15;
    const float* hdB = g_hd + ((size_t)b << 16);

    // he + b1 -> sHE
    if (t < 128){
        float4 h  = ((const float4*)(g_he + (size_t)bm*Ddim))[t];
        float4 bb = ((const float4*)b1)[t];
        float4 v; v.x = h.x+bb.x; v.y = h.y+bb.y; v.z = h.z+bb.z; v.w = h.w+bb.w;
        ((float4*)sHE)[t] = v;
    }
    // B chunk 0 (pass 0) -> stage 0
#pragma unroll
    for (int j = 0; j < 4; j++)
        cpa16(sBp + (j << 6)*PITCH, bG + ((size_t)(j << 6) << 10));
    CPA_COMMIT();

    // prefetch hd for chunk 0 (registers; latency overlaps prologue sync)
    float4 hdr[4];
#pragma unroll
    for (int i = 0; i < 4; i++)
        hdr[i] = *(const float4*)(hdB + (size_t)(arb + (i << 5))*Ddim + (af4 << 2));

    __syncthreads();      // sHE visible for A production

    float m8[8], s8[8];
#pragma unroll
    for (int i = 0; i < 8; i++){ m8[i] = -3.4e38f; s8[i] = 0.f; }
    float acc[4][4][4];   // [mt][nt][frag]

#pragma unroll 1
    for (int q = 0; q < 32; q++){
        const int pass = q >> 3, kc = q & 7, buf = q & 1;

        // pass 0: produce A chunk q from prefetched hd regs (no LDG stall here)
        if (q < 8){
            char* dA = smemc + q*ACHUNK;
            float4 h = *(const float4*)(sHE + (q << 6) + (af4 << 2));
#pragma unroll
            for (int i = 0; i < 4; i++){
                const int row = arb + (i << 5);
                float4 d = hdr[i];
                uint2 o;
                o.x = pk(tanh_fast(h.x + d.x), tanh_fast(h.y + d.y));
                o.y = pk(tanh_fast(h.z + d.z), tanh_fast(h.w + d.w));
                *(uint2*)(dA + row*PITCH + (af4 << 3)) = o;
            }
        }

        CPA_WAIT0();          // B stage q&1 complete
        __syncthreads();      // all copies + A production visible

        // issue B copy for q+1 into the other stage
        if (q < 31){
            const int qn = q + 1, pn = qn >> 3, kn = qn & 7;
            const char* bsrc = bG + ((size_t)(pn << 8) << 10) + (kn << 7);
            const unsigned bdst = sBp + (qn & 1)*B_BUF;
#pragma unroll
            for (int j = 0; j < 4; j++)
                cpa16(bdst + (j << 6)*PITCH, bsrc + ((size_t)(j << 6) << 10));
            CPA_COMMIT();
        }

        // issue hd LDGs for chunk q+1 (latency hidden under this chunk's mma)
        if (q < 7){
            const int ko = ((q + 1) << 6) + (af4 << 2);
#pragma unroll
            for (int i = 0; i < 4; i++)
                hdr[i] = *(const float4*)(hdB + (size_t)(arb + (i << 5))*Ddim + ko);
        }

        if (kc == 0){
#pragma unroll
            for (int mt = 0; mt < 4; mt++)
#pragma unroll
                for (int nt = 0; nt < 4; nt++)
#pragma unroll
                    for (int i = 0; i < 4; i++) acc[mt][nt][i] = 0.f;
        }

        // mma over chunk kc (4 k16 steps), ldmatrix fragment loads
        const unsigned aCh = sb + kc*ACHUNK + aBase;
        const unsigned bCh = sb + SB_OFF + buf*B_BUF + bBase;
#pragma unroll
        for (int s = 0; s < 4; s++){
            const unsigned off = s << 5;
            unsigned af[4][4], bq[2][4];
#pragma unroll
            for (int mt = 0; mt < 4; mt++)
                ldsm4(af[mt], aCh + (mt << 4)*PITCH + off);
#pragma unroll
            for (int np = 0; np < 2; np++)
                ldsm4(bq[np], bCh + (np << 4)*PITCH + off);
#pragma unroll
            for (int mt = 0; mt < 4; mt++)
#pragma unroll
                for (int nt = 0; nt < 4; nt++)
                    mma_bf16(acc[mt][nt], af[mt], &bq[nt >> 1][(nt & 1) << 1]);
        }

        // pass epilogue: +b2, write logits, merge online (max, sumexp)
        if (kc == 7){
            const int colb = (pass << 8) + (wn << 5);
#pragma unroll
            for (int mt = 0; mt < 4; mt++){
#pragma unroll
                for (int h = 0; h < 2; h++){
                    const int r = (wm << 6) + (mt << 4) + lq + (h << 3);
                    const int g = g0 + r;
                    float v[8];
                    float gm = -3.4e38f;
#pragma unroll
                    for (int nt = 0; nt < 4; nt++){
                        const int c = colb + (nt << 3) + (lr << 1);
                        float x0 = acc[mt][nt][h*2 + 0] + __ldg(b2 + c);
                        float x1 = acc[mt][nt][h*2 + 1] + __ldg(b2 + c + 1);
                        v[2*nt] = x0; v[2*nt + 1] = x1;
                        gm = fmaxf(gm, fmaxf(x0, x1));
                        float2 st; st.x = x0; st.y = x1;
                        *(float2*)(out + (size_t)g*Cdim + c) = st;
                    }
                    float gs = 0.f;
#pragma unroll
                    for (int i = 0; i < 8; i++) gs += __expf(v[i] - gm);
                    const int slot = (mt << 1) + h;
                    float mn = fmaxf(m8[slot], gm);
                    s8[slot] = s8[slot]*__expf(m8[slot] - mn) + gs*__expf(gm - mn);
                    m8[slot] = mn;
                }
            }
        }
    }

    // ---- cross-lane (lr) reduction of (m, s) ----
#pragma unroll
    for (int i = 0; i < 8; i++){
#pragma unroll
        for (int k = 1; k <= 2; k <<= 1){
            float om = __shfl_xor_sync(0xffffffffu, m8[i], k);
            float os = __shfl_xor_sync(0xffffffffu, s8[i], k);
            float mn = fmaxf(m8[i], om);
            s8[i] = s8[i]*__expf(m8[i] - mn) + os*__expf(om - mn);
            m8[i] = mn;
        }
    }
    __syncthreads();   // B stages dead; reuse as reduction area
    float* sred = (float*)(smemc + SB_OFF);          // [128][8] float2
    float* slse = (float*)(smemc + SB_OFF + 8192);   // [128]
    if (lr == 0){
#pragma unroll
        for (int i = 0; i < 8; i++){
            const int r = (wm << 6) + ((i >> 1) << 4) + lq + ((i & 1) << 3);
            float2 p; p.x = m8[i]; p.y = s8[i];
            *(float2*)(sred + ((r << 3) + wn)*2) = p;
        }
    }
    __syncthreads();
    if (t < 128){
        const float2* p = (const float2*)(sred + (t << 4));
        float mx = -3.4e38f;
#pragma unroll
        for (int i = 0; i < 8; i++) mx = fmaxf(mx, p[i].x);
        float s = 0.f;
#pragma unroll
        for (int i = 0; i < 8; i++) s += p[i].y*__expf(p[i].x - mx);
        slse[t] = mx + __logf(s);
    }
    __syncthreads();

    // ---- final: out -= lse (tile is L2-hot) ----
    float4* outB = (float4*)out + ((size_t)g0 << 8);   // 256 float4 per row
#pragma unroll 4
    for (int i = t; i < 128*256; i += 512){
        const float lse = slse[i >> 8];
        float4 v = outB[i];
        v.x -= lse; v.y -= lse; v.z -= lse; v.w -= lse;
        __stcs(outB + i, v);
    }
}

// ================= launch =================
extern "C" void kernel_launch(void* const* d_in, const int* in_sizes, int n_in,
                              void* d_out, int out_size){
    (void)in_sizes; (void)n_in; (void)out_size;
    const float* enc = (const float*)d_in[0];
    const float* dec = (const float*)d_in[1];
    const float* w1  = (const float*)d_in[2];
    const float* b1  = (const float*)d_in[3];
    const float* w2  = (const float*)d_in[4];
    const float* b2  = (const float*)d_in[5];
    float* out = (float*)d_out;

    cudaFuncSetAttribute(fused_k, cudaFuncAttributeMaxDynamicSharedMemorySize, SMEM_TOT);

    cvtw2b_k<<<(Cdim*Ddim/8)/256, 256>>>(w2);
    fc1_k<<<dim3(8, 24), 256>>>(enc, dec, w1);
    fused_k<<<1024, 512, SMEM_TOT>>>(b1, b2, out);
}

// round 15
// speedup vs baseline: 1.0288x; 1.0288x over previous
#include <cuda_runtime.h>
#include <cuda_bf16.h>
#include <cstdint>

// Problem dims
#define Bdim 4
#define Mdim 256
#define Ndim 128
#define Ddim 512
#define Cdim 1024
#define ROWS (Bdim*Mdim*Ndim)   // 131072

// -------- scratch (device globals) --------
__device__ float g_he[Bdim*Mdim*Ddim];          // 2 MB
__device__ float g_hd[Bdim*Ndim*Ddim];          // 1 MB
__device__ __nv_bfloat16 g_w2b[Cdim*Ddim];      // 1 MB   w2 -> bf16

// -------- helpers --------
__device__ __forceinline__ float tanh_fast(float x){
    float r; asm("tanh.approx.f32 %0, %1;" : "=f"(r) : "f"(x)); return r;
}
__device__ __forceinline__ unsigned pk(float lo, float hi){
    unsigned r;
    asm("cvt.rn.bf16x2.f32 %0, %2, %1;" : "=r"(r) : "f"(lo), "f"(hi));
    return r;
}
__device__ __forceinline__ void mma_bf16(float* d, const unsigned* a, const unsigned* b){
    asm volatile(
        "mma.sync.aligned.m16n8k16.row.col.f32.bf16.bf16.f32 "
        "{%0,%1,%2,%3}, {%4,%5,%6,%7}, {%8,%9}, {%0,%1,%2,%3};\n"
        : "+f"(d[0]), "+f"(d[1]), "+f"(d[2]), "+f"(d[3])
        : "r"(a[0]), "r"(a[1]), "r"(a[2]), "r"(a[3]), "r"(b[0]), "r"(b[1]));
}
__device__ __forceinline__ void ldsm4(unsigned* r, unsigned addr){
    asm volatile("ldmatrix.sync.aligned.m8n8.x4.shared.b16 {%0,%1,%2,%3}, [%4];"
        : "=r"(r[0]), "=r"(r[1]), "=r"(r[2]), "=r"(r[3]) : "r"(addr));
}
__device__ __forceinline__ unsigned smem_u32(const void* p){
    unsigned a;
    asm("{ .reg .u64 t; cvta.to.shared.u64 t, %1; cvt.u32.u64 %0, t; }" : "=r"(a) : "l"(p));
    return a;
}
__device__ __forceinline__ void cpa16(unsigned saddr, const void* g){
    asm volatile("cp.async.cg.shared.global [%0], [%1], 16;" :: "r"(saddr), "l"(g));
}
#define CPA_COMMIT() asm volatile("cp.async.commit_group;" ::: "memory")
#define CPA_WAIT0()  asm volatile("cp.async.wait_group 0;" ::: "memory")

// ================= K0: w2 -> bf16 =================
__global__ __launch_bounds__(256) void cvtw2b_k(const float* __restrict__ w2){
    const int i = blockIdx.x*256 + threadIdx.x;
    float4 v0 = ((const float4*)w2)[2*i];
    float4 v1 = ((const float4*)w2)[2*i + 1];
    uint4 o;
    o.x = pk(v0.x, v0.y); o.y = pk(v0.z, v0.w);
    o.z = pk(v1.x, v1.y); o.w = pk(v1.z, v1.w);
    ((uint4*)g_w2b)[i] = o;
}

// ================= K1: fc1 both GEMMs in one launch (fp32, exact) ==============
__global__ __launch_bounds__(256) void fc1_k(const float* __restrict__ enc,
                                             const float* __restrict__ dec,
                                             const float* __restrict__ W){
    __shared__ float sX[16][64];
    __shared__ float sW[16][64];
    const int by = blockIdx.y;
    const int which = (by >= 16);
    const float* __restrict__ X = which ? dec : enc;
    float* __restrict__ Y = which ? g_hd : g_he;
    const int woff = which ? Ddim : 0;
    const int rb = (which ? (by - 16) : by) << 6;
    const int t  = threadIdx.x;
    const int tx = t & 15, ty = t >> 4;
    const int eb = blockIdx.x << 6;
    const int r  = t >> 2, kq = (t & 3) << 2;

    float acc[4][4];
#pragma unroll
    for (int i = 0; i < 4; i++)
#pragma unroll
        for (int j = 0; j < 4; j++) acc[i][j] = 0.f;

    for (int k0 = 0; k0 < Ddim; k0 += 16){
        float4 xv = *(const float4*)(X + (rb + r)*Ddim + k0 + kq);
        float4 wv = *(const float4*)(W + (eb + r)*(2*Ddim) + woff + k0 + kq);
        __syncthreads();
        sX[kq+0][r] = xv.x; sX[kq+1][r] = xv.y; sX[kq+2][r] = xv.z; sX[kq+3][r] = xv.w;
        sW[kq+0][r] = wv.x; sW[kq+1][r] = wv.y; sW[kq+2][r] = wv.z; sW[kq+3][r] = wv.w;
        __syncthreads();
#pragma unroll
        for (int k = 0; k < 16; k++){
            float4 a  = *(const float4*)&sX[k][ty << 2];
            float4 bv = *(const float4*)&sW[k][tx << 2];
            float av[4] = {a.x, a.y, a.z, a.w};
            float bb[4] = {bv.x, bv.y, bv.z, bv.w};
#pragma unroll
            for (int i = 0; i < 4; i++)
#pragma unroll
                for (int j = 0; j < 4; j++) acc[i][j] = fmaf(av[i], bb[j], acc[i][j]);
        }
    }
#pragma unroll
    for (int i = 0; i < 4; i++)
#pragma unroll
        for (int j = 0; j < 4; j++)
            Y[(rb + (ty<<2) + i)*Ddim + eb + (tx<<2) + j] = acc[i][j];
}

// ================= K2: fused tanh + GEMM + log-softmax =========================
// One CTA per bm (grid 1024), 512 threads, 16 warps as 2(m) x 8(n),
// warp tile 64x32. 128 rows x ALL 1024 cols in 4 col-passes of 256.
// K=512 in 8 chunks of 64. A produced in-kernel (pass 0) and resident.
// smem: sA 8x18432 = 147456, sB 2x36864 = 73728, sHE 2048, sB2 4096 (= 227328)
#define PITCH   144
#define ACHUNK  18432
#define SB_OFF  147456
#define B_BUF   36864
#define SHE_OFF 221184
#define SB2_OFF 223232
#define SMEM_TOT 227328

__global__ __launch_bounds__(512,1) void fused_k(const float* __restrict__ b1,
                                                 const float* __restrict__ b2,
                                                 float* __restrict__ out){
    extern __shared__ __align__(128) char smemc[];
    const unsigned sb = smem_u32(smemc);

    const int bm  = blockIdx.x;     // 0..1023
    const int g0  = bm << 7;        // first global row
    const int b   = bm >> 8;        // batch
    const int t   = threadIdx.x;
    const int w   = t >> 5, l = t & 31;
    const int wm  = w >> 3, wn = w & 7;      // 2(m) x 8(n)
    const int lq  = l >> 2, lr = l & 3;

    float* sHE = (float*)(smemc + SHE_OFF);
    const float* sB2 = (const float*)(smemc + SB2_OFF);

    // ldmatrix per-lane base offsets
    const unsigned aLane = (unsigned)((l & 15)*PITCH + (l & 16));
    const unsigned bLane = (unsigned)(((l & 7) + ((l & 16) >> 1))*PITCH + ((l & 8) << 1));
    const unsigned aBase = (unsigned)((wm << 6)*PITCH) + aLane;
    const unsigned bBase = (unsigned)((wn << 5)*PITCH) + bLane;

    // B producer mapping: 8 threads per 128B row chunk; rows (t>>3) + 64j, j<4
    const int pr  = t >> 3;          // 0..63
    const int pc  = (t & 7) << 4;
    const char* bG = (const char*)g_w2b + ((size_t)pr << 10) + pc;
    const unsigned sBp = sb + SB_OFF + pr*PITCH + pc;

    // A producer mapping: rows (t>>4) + 32i (i<4), float4 slot t&15
    const int arb = t >> 4;          // 0..31
    const int af4 = t & 15;
    const float* hdB = g_hd + ((size_t)b << 16);

    // he + b1 -> sHE ; b2 -> sB2
    if (t < 128){
        float4 h  = ((const float4*)(g_he + (size_t)bm*Ddim))[t];
        float4 bb = ((const float4*)b1)[t];
        float4 v; v.x = h.x+bb.x; v.y = h.y+bb.y; v.z = h.z+bb.z; v.w = h.w+bb.w;
        ((float4*)sHE)[t] = v;
    }
    if (t < 256)
        ((float4*)(smemc + SB2_OFF))[t] = ((const float4*)b2)[t];

    // B chunk 0 (pass 0) -> stage 0
#pragma unroll
    for (int j = 0; j < 4; j++)
        cpa16(sBp + (j << 6)*PITCH, bG + ((size_t)(j << 6) << 10));
    CPA_COMMIT();
    __syncthreads();      // sHE + sB2 visible

    float m8[8], s8[8];
#pragma unroll
    for (int i = 0; i < 8; i++){ m8[i] = -3.4e38f; s8[i] = 0.f; }
    float acc[4][4][4];   // [mt][nt][frag]

#pragma unroll 1
    for (int q = 0; q < 32; q++){
        const int pass = q >> 3, kc = q & 7, buf = q & 1;

        // pass 0: produce A chunk q = bf16(tanh(he + b1 + hd)) into resident sA
        if (q < 8){
            char* dA = smemc + q*ACHUNK;
            float4 h = *(const float4*)(sHE + (q << 6) + (af4 << 2));
#pragma unroll
            for (int i = 0; i < 4; i++){
                const int row = arb + (i << 5);
                float4 d = *(const float4*)(hdB + (size_t)row*Ddim + (q << 6) + (af4 << 2));
                uint2 o;
                o.x = pk(tanh_fast(h.x + d.x), tanh_fast(h.y + d.y));
                o.y = pk(tanh_fast(h.z + d.z), tanh_fast(h.w + d.w));
                *(uint2*)(dA + row*PITCH + (af4 << 3)) = o;
            }
        }

        CPA_WAIT0();          // B stage q&1 complete
        __syncthreads();      // all copies + A production visible

        // issue B copy for q+1 into the other stage
        if (q < 31){
            const int qn = q + 1, pn = qn >> 3, kn = qn & 7;
            const char* bsrc = bG + ((size_t)(pn << 8) << 10) + (kn << 7);
            const unsigned bdst = sBp + (qn & 1)*B_BUF;
#pragma unroll
            for (int j = 0; j < 4; j++)
                cpa16(bdst + (j << 6)*PITCH, bsrc + ((size_t)(j << 6) << 10));
            CPA_COMMIT();
        }

        if (kc == 0){
#pragma unroll
            for (int mt = 0; mt < 4; mt++)
#pragma unroll
                for (int nt = 0; nt < 4; nt++)
#pragma unroll
                    for (int i = 0; i < 4; i++) acc[mt][nt][i] = 0.f;
        }

        // mma over chunk kc (4 k16 steps), ldmatrix fragment loads
        const unsigned aCh = sb + kc*ACHUNK + aBase;
        const unsigned bCh = sb + SB_OFF + buf*B_BUF + bBase;
#pragma unroll
        for (int s = 0; s < 4; s++){
            const unsigned off = s << 5;
            unsigned af[4][4], bq[2][4];
#pragma unroll
            for (int mt = 0; mt < 4; mt++)
                ldsm4(af[mt], aCh + (mt << 4)*PITCH + off);
#pragma unroll
            for (int np = 0; np < 2; np++)
                ldsm4(bq[np], bCh + (np << 4)*PITCH + off);
#pragma unroll
            for (int mt = 0; mt < 4; mt++)
#pragma unroll
                for (int nt = 0; nt < 4; nt++)
                    mma_bf16(acc[mt][nt], af[mt], &bq[nt >> 1][(nt & 1) << 1]);
        }

        // pass epilogue: +b2, write logits, merge online (max, sumexp)
        if (kc == 7){
            const int colb = (pass << 8) + (wn << 5);
            float bb[8];
#pragma unroll
            for (int nt = 0; nt < 4; nt++){
                bb[2*nt]     = sB2[colb + (nt << 3) + (lr << 1)];
                bb[2*nt + 1] = sB2[colb + (nt << 3) + (lr << 1) + 1];
            }
#pragma unroll
            for (int mt = 0; mt < 4; mt++){
#pragma unroll
                for (int h = 0; h < 2; h++){
                    const int r = (wm << 6) + (mt << 4) + lq + (h << 3);
                    const int g = g0 + r;
                    float v[8];
                    float gm = -3.4e38f;
#pragma unroll
                    for (int nt = 0; nt < 4; nt++){
                        const int c = colb + (nt << 3) + (lr << 1);
                        float x0 = acc[mt][nt][h*2 + 0] + bb[2*nt];
                        float x1 = acc[mt][nt][h*2 + 1] + bb[2*nt + 1];
                        v[2*nt] = x0; v[2*nt + 1] = x1;
                        gm = fmaxf(gm, fmaxf(x0, x1));
                        float2 st; st.x = x0; st.y = x1;
                        *(float2*)(out + (size_t)g*Cdim + c) = st;
                    }
                    float gs = 0.f;
#pragma unroll
                    for (int i = 0; i < 8; i++) gs += __expf(v[i] - gm);
                    const int slot = (mt << 1) + h;
                    float mn = fmaxf(m8[slot], gm);
                    s8[slot] = s8[slot]*__expf(m8[slot] - mn) + gs*__expf(gm - mn);
                    m8[slot] = mn;
                }
            }
        }
    }

    // ---- cross-lane (lr) reduction of (m, s) ----
#pragma unroll
    for (int i = 0; i < 8; i++){
#pragma unroll
        for (int k = 1; k <= 2; k <<= 1){
            float om = __shfl_xor_sync(0xffffffffu, m8[i], k);
            float os = __shfl_xor_sync(0xffffffffu, s8[i], k);
            float mn = fmaxf(m8[i], om);
            s8[i] = s8[i]*__expf(m8[i] - mn) + os*__expf(om - mn);
            m8[i] = mn;
        }
    }
    __syncthreads();   // B stages dead; reuse as reduction area
    float* sred = (float*)(smemc + SB_OFF);          // [128][8] float2
    float* slse = (float*)(smemc + SB_OFF + 8192);   // [128]
    if (lr == 0){
#pragma unroll
        for (int i = 0; i < 8; i++){
            const int r = (wm << 6) + ((i >> 1) << 4) + lq + ((i & 1) << 3);
            float2 p; p.x = m8[i]; p.y = s8[i];
            *(float2*)(sred + ((r << 3) + wn)*2) = p;
        }
    }
    __syncthreads();
    if (t < 128){
        const float2* p = (const float2*)(sred + (t << 4));
        float mx = -3.4e38f;
#pragma unroll
        for (int i = 0; i < 8; i++) mx = fmaxf(mx, p[i].x);
        float s = 0.f;
#pragma unroll
        for (int i = 0; i < 8; i++) s += p[i].y*__expf(p[i].x - mx);
        slse[t] = mx + __logf(s);
    }
    __syncthreads();

    // ---- final: out -= lse (tile is L2-hot) ----
    float4* outB = (float4*)out + ((size_t)g0 << 8);   // 256 float4 per row
#pragma unroll 4
    for (int i = t; i < 128*256; i += 512){
        const float lse = slse[i >> 8];
        float4 v = outB[i];
        v.x -= lse; v.y -= lse; v.z -= lse; v.w -= lse;
        __stcs(outB + i, v);
    }
}

// ================= launch =================
extern "C" void kernel_launch(void* const* d_in, const int* in_sizes, int n_in,
                              void* d_out, int out_size){
    (void)in_sizes; (void)n_in; (void)out_size;
    const float* enc = (const float*)d_in[0];
    const float* dec = (const float*)d_in[1];
    const float* w1  = (const float*)d_in[2];
    const float* b1  = (const float*)d_in[3];
    const float* w2  = (const float*)d_in[4];
    const float* b2  = (const float*)d_in[5];
    float* out = (float*)d_out;

    cudaFuncSetAttribute(fused_k, cudaFuncAttributeMaxDynamicSharedMemorySize, SMEM_TOT);

    cvtw2b_k<<<(Cdim*Ddim/8)/256, 256>>>(w2);
    fc1_k<<<dim3(8, 24), 256>>>(enc, dec, w1);
    fused_k<<<1024, 512, SMEM_TOT>>>(b1, b2, out);
}